// round 1
// baseline (speedup 1.0000x reference)
#include <cuda_runtime.h>
#include <cuda_bf16.h>
#include <cstddef>

#define BATCH 4
#define CC    512
#define OO    64
#define NN    4096

// ---------------- scratch (device globals; allocation-free) ----------------
__device__ float d_f[BATCH * OO * NN];            // 4 MiB
__device__ float d_g[BATCH * OO * NN];            // 4 MiB
__device__ float d_h[BATCH * CC * NN];            // 32 MiB
__device__ float d_scores[(size_t)BATCH * NN * NN]; // 256 MiB
__device__ float d_colmax[BATCH * NN];
__device__ float d_colsum[BATCH * NN];

// ---------------------------------------------------------------------------
// proj: out[b,m,n] = sum_k W[m,k] * x[b,k,n] + bias[m]
// 64x64x16 tile, 256 threads, 4x4 micro-tile
// grid: (NN/64, M/64, BATCH)
// ---------------------------------------------------------------------------
__global__ __launch_bounds__(256)
void proj_kernel(const float* __restrict__ W, const float* __restrict__ bias,
                 const float* __restrict__ x, float* __restrict__ out,
                 int M, int K)
{
    __shared__ float As[16][68];  // [k][m], padded (row = 272B, 16B-aligned)
    __shared__ float Bs[16][68];  // [k][n]

    const int b  = blockIdx.z;
    const int m0 = blockIdx.y * 64;
    const int n0 = blockIdx.x * 64;
    const int tid = threadIdx.x;
    const int tx = tid & 15, ty = tid >> 4;

    const float* xb = x + (size_t)b * K * NN;

    float acc[4][4] = {};

    for (int k0 = 0; k0 < K; k0 += 16) {
        // A tile: 64 rows (m) x 16 cols (k), stored transposed As[k][m]
        #pragma unroll
        for (int r = 0; r < 4; r++) {
            int lin = tid + r * 256;
            int m = lin >> 4, k = lin & 15;
            As[k][m] = W[(size_t)(m0 + m) * K + k0 + k];
        }
        // B tile: 16 rows (k) x 64 cols (n), coalesced along n
        #pragma unroll
        for (int r = 0; r < 4; r++) {
            int lin = tid + r * 256;
            int k = lin >> 6, n = lin & 63;
            Bs[k][n] = xb[(size_t)(k0 + k) * NN + n0 + n];
        }
        __syncthreads();

        #pragma unroll
        for (int kk = 0; kk < 16; kk++) {
            float4 av = *(const float4*)&As[kk][ty * 4];
            float4 bv = *(const float4*)&Bs[kk][tx * 4];
            float a[4] = {av.x, av.y, av.z, av.w};
            float c[4] = {bv.x, bv.y, bv.z, bv.w};
            #pragma unroll
            for (int i = 0; i < 4; i++)
                #pragma unroll
                for (int j = 0; j < 4; j++)
                    acc[i][j] += a[i] * c[j];
        }
        __syncthreads();
    }

    #pragma unroll
    for (int i = 0; i < 4; i++) {
        int m = m0 + ty * 4 + i;
        float bb = bias[m];
        float4 v = make_float4(acc[i][0] + bb, acc[i][1] + bb,
                               acc[i][2] + bb, acc[i][3] + bb);
        *(float4*)&out[(size_t)b * M * NN + (size_t)m * NN + n0 + tx * 4] = v;
    }
}

// ---------------------------------------------------------------------------
// scores[b,i,j] = sum_o f[b,o,i] * g[b,o,j]
// 128x128, K=64 (4 x BK=16), 256 threads, 8x8 micro-tile
// grid: (NN/128 [j], NN/128 [i], BATCH)
// ---------------------------------------------------------------------------
__global__ __launch_bounds__(256)
void scores_kernel(const float* __restrict__ f, const float* __restrict__ g,
                   float* __restrict__ scores)
{
    __shared__ float As[16][132];  // [o][i]
    __shared__ float Bs[16][132];  // [o][j]

    const int b  = blockIdx.z;
    const int i0 = blockIdx.y * 128;
    const int j0 = blockIdx.x * 128;
    const int tid = threadIdx.x;
    const int tx = tid & 15, ty = tid >> 4;

    const float* fb = f + (size_t)b * OO * NN;
    const float* gb = g + (size_t)b * OO * NN;

    float acc[8][8] = {};

    for (int o0 = 0; o0 < OO; o0 += 16) {
        // both operands are [o][pos] with stride NN: direct coalesced loads
        #pragma unroll
        for (int r = 0; r < 8; r++) {
            int lin = tid + r * 256;
            int o = lin >> 7, p = lin & 127;
            As[o][p] = fb[(size_t)(o0 + o) * NN + i0 + p];
            Bs[o][p] = gb[(size_t)(o0 + o) * NN + j0 + p];
        }
        __syncthreads();

        #pragma unroll
        for (int kk = 0; kk < 16; kk++) {
            float4 a0 = *(const float4*)&As[kk][ty * 8];
            float4 a1 = *(const float4*)&As[kk][ty * 8 + 4];
            float4 b0 = *(const float4*)&Bs[kk][tx * 8];
            float4 b1 = *(const float4*)&Bs[kk][tx * 8 + 4];
            float a[8] = {a0.x, a0.y, a0.z, a0.w, a1.x, a1.y, a1.z, a1.w};
            float c[8] = {b0.x, b0.y, b0.z, b0.w, b1.x, b1.y, b1.z, b1.w};
            #pragma unroll
            for (int i = 0; i < 8; i++)
                #pragma unroll
                for (int j = 0; j < 8; j++)
                    acc[i][j] += a[i] * c[j];
        }
        __syncthreads();
    }

    float* sb = scores + (size_t)b * NN * NN;
    #pragma unroll
    for (int i = 0; i < 8; i++) {
        size_t row = (size_t)(i0 + ty * 8 + i) * NN + j0 + tx * 8;
        *(float4*)&sb[row]     = make_float4(acc[i][0], acc[i][1], acc[i][2], acc[i][3]);
        *(float4*)&sb[row + 4] = make_float4(acc[i][4], acc[i][5], acc[i][6], acc[i][7]);
    }
}

// ---------------------------------------------------------------------------
// colstat: per (b,j) compute max_i scores[b,i,j] and sum_i exp(s - max)
// grid: (NN/256, BATCH), block 256; coalesced across j
// ---------------------------------------------------------------------------
__global__ __launch_bounds__(256)
void colstat_kernel(const float* __restrict__ scores,
                    float* __restrict__ colmax, float* __restrict__ colsum)
{
    const int b = blockIdx.y;
    const int j = blockIdx.x * 256 + threadIdx.x;
    const float* s = scores + (size_t)b * NN * NN + j;

    float m = -3.4e38f, sum = 0.0f;
    #pragma unroll 4
    for (int i = 0; i < NN; i++) {
        float v = s[(size_t)i * NN];
        if (v > m) {
            sum = sum * __expf(m - v) + 1.0f;
            m = v;
        } else {
            sum += __expf(v - m);
        }
    }
    colmax[b * NN + j] = m;
    colsum[b * NN + j] = sum;
}

// ---------------------------------------------------------------------------
// attn: out[b,c,m] = gamma * (sum_n h[b,c,n] * exp(scores[b,n,m]-max[m])) / sum[m]
//                    + x[b,c,m]
// 128x128x16 tile, 256 threads, 8x8 micro-tile
// grid: (NN/128 [m], CC/128 [c], BATCH)
// ---------------------------------------------------------------------------
__global__ __launch_bounds__(256)
void attn_kernel(const float* __restrict__ h, const float* __restrict__ scores,
                 const float* __restrict__ colmax, const float* __restrict__ colsum,
                 const float* __restrict__ x, const float* __restrict__ gamma_p,
                 float* __restrict__ out)
{
    __shared__ float As[16][132];   // [k][c]  (h transposed tile)
    __shared__ float Bs[16][132];   // [k][m]  (exp(scores - max))
    __shared__ float s_max[128], s_inv[128];

    const int b  = blockIdx.z;
    const int c0 = blockIdx.y * 128;
    const int m0 = blockIdx.x * 128;
    const int tid = threadIdx.x;
    const int tx = tid & 15, ty = tid >> 4;

    if (tid < 128) {
        s_max[tid] = colmax[b * NN + m0 + tid];
        s_inv[tid] = 1.0f / colsum[b * NN + m0 + tid];
    }
    __syncthreads();

    const float* hb = h + (size_t)b * CC * NN;
    const float* sb = scores + (size_t)b * NN * NN;

    float acc[8][8] = {};

    for (int k0 = 0; k0 < NN; k0 += 16) {
        // A: h[c0+c][k0+k] -> As[k][c] (transpose in smem)
        #pragma unroll
        for (int r = 0; r < 8; r++) {
            int lin = tid + r * 256;
            int c = lin >> 4, k = lin & 15;
            As[k][c] = hb[(size_t)(c0 + c) * NN + k0 + k];
        }
        // B: p[k][m] = exp(scores[k0+k][m0+m] - max[m]); coalesced along m
        #pragma unroll
        for (int r = 0; r < 8; r++) {
            int lin = tid + r * 256;
            int k = lin >> 7, m = lin & 127;
            Bs[k][m] = __expf(sb[(size_t)(k0 + k) * NN + m0 + m] - s_max[m]);
        }
        __syncthreads();

        #pragma unroll
        for (int kk = 0; kk < 16; kk++) {
            float4 a0 = *(const float4*)&As[kk][ty * 8];
            float4 a1 = *(const float4*)&As[kk][ty * 8 + 4];
            float4 b0 = *(const float4*)&Bs[kk][tx * 8];
            float4 b1 = *(const float4*)&Bs[kk][tx * 8 + 4];
            float a[8] = {a0.x, a0.y, a0.z, a0.w, a1.x, a1.y, a1.z, a1.w};
            float c[8] = {b0.x, b0.y, b0.z, b0.w, b1.x, b1.y, b1.z, b1.w};
            #pragma unroll
            for (int i = 0; i < 8; i++)
                #pragma unroll
                for (int j = 0; j < 8; j++)
                    acc[i][j] += a[i] * c[j];
        }
        __syncthreads();
    }

    const float gamma = *gamma_p;
    #pragma unroll
    for (int i = 0; i < 8; i++) {
        int c = c0 + ty * 8 + i;
        size_t base = (size_t)b * CC * NN + (size_t)c * NN + m0 + tx * 8;
        float4 x0 = *(const float4*)&x[base];
        float4 x1 = *(const float4*)&x[base + 4];
        float4 o0, o1;
        o0.x = gamma * acc[i][0] * s_inv[tx * 8 + 0] + x0.x;
        o0.y = gamma * acc[i][1] * s_inv[tx * 8 + 1] + x0.y;
        o0.z = gamma * acc[i][2] * s_inv[tx * 8 + 2] + x0.z;
        o0.w = gamma * acc[i][3] * s_inv[tx * 8 + 3] + x0.w;
        o1.x = gamma * acc[i][4] * s_inv[tx * 8 + 4] + x1.x;
        o1.y = gamma * acc[i][5] * s_inv[tx * 8 + 5] + x1.y;
        o1.z = gamma * acc[i][6] * s_inv[tx * 8 + 6] + x1.z;
        o1.w = gamma * acc[i][7] * s_inv[tx * 8 + 7] + x1.w;
        *(float4*)&out[base]     = o0;
        *(float4*)&out[base + 4] = o1;
    }
}

// ---------------------------------------------------------------------------
extern "C" void kernel_launch(void* const* d_in, const int* in_sizes, int n_in,
                              void* d_out, int out_size)
{
    const float* x     = (const float*)d_in[0];
    const float* f_w   = (const float*)d_in[1];
    const float* f_b   = (const float*)d_in[2];
    const float* g_w   = (const float*)d_in[3];
    const float* g_b   = (const float*)d_in[4];
    const float* h_w   = (const float*)d_in[5];
    const float* h_b   = (const float*)d_in[6];
    const float* gamma = (const float*)d_in[7];
    float* out = (float*)d_out;

    float *pf, *pg, *ph, *ps, *pmax, *psum;
    cudaGetSymbolAddress((void**)&pf,   d_f);
    cudaGetSymbolAddress((void**)&pg,   d_g);
    cudaGetSymbolAddress((void**)&ph,   d_h);
    cudaGetSymbolAddress((void**)&ps,   d_scores);
    cudaGetSymbolAddress((void**)&pmax, d_colmax);
    cudaGetSymbolAddress((void**)&psum, d_colsum);

    dim3 blk(256);

    // f, g projections: M=64, K=512
    proj_kernel<<<dim3(NN / 64, 1, BATCH), blk>>>(f_w, f_b, x, pf, OO, CC);
    proj_kernel<<<dim3(NN / 64, 1, BATCH), blk>>>(g_w, g_b, x, pg, OO, CC);
    // h projection: M=512, K=512
    proj_kernel<<<dim3(NN / 64, CC / 64, BATCH), blk>>>(h_w, h_b, x, ph, CC, CC);

    // scores
    scores_kernel<<<dim3(NN / 128, NN / 128, BATCH), blk>>>(pf, pg, ps);

    // column softmax stats
    colstat_kernel<<<dim3(NN / 256, BATCH), blk>>>(ps, pmax, psum);

    // attention GEMM + epilogue
    attn_kernel<<<dim3(NN / 128, CC / 128, BATCH), blk>>>(
        ph, ps, pmax, psum, x, gamma, out);
}

// round 3
// speedup vs baseline: 4.7260x; 4.7260x over previous
#include <cuda_runtime.h>
#include <cuda_bf16.h>
#include <cstdint>
#include <cstddef>

#define BATCH 4
#define CC    512
#define OO    64
#define NN    4096

// ---------------- scratch (device globals; allocation-free) ----------------
__device__ __nv_bfloat16 d_xT [BATCH * NN * CC];      // x transposed [b][n][k] bf16
__device__ __nv_bfloat16 d_fgw[128 * CC];             // stacked [f_w; g_w] bf16
__device__ __nv_bfloat16 d_hw [CC * CC];              // h_w bf16
__device__ __nv_bfloat16 d_fT [BATCH * NN * OO];      // f transposed [b][i][o]
__device__ __nv_bfloat16 d_gT [BATCH * NN * OO];      // g transposed [b][j][o]
__device__ __nv_bfloat16 d_hB [BATCH * CC * NN];      // h bf16 [b][c][n]
__device__ float d_scores[(size_t)BATCH * NN * NN];   // fp32 scores [b][i][j]
__device__ float d_colmax[BATCH * NN];
__device__ float d_colinv[BATCH * NN];
__device__ __nv_bfloat16 d_probT[(size_t)BATCH * NN * NN]; // probs^T [b][m][n] bf16

// ------------------------- helpers -----------------------------------------
__device__ __forceinline__ uint32_t smem_u32(const void* p) {
    uint32_t a;
    asm("{ .reg .u64 t; cvta.to.shared.u64 t, %1; cvt.u32.u64 %0, t; }"
        : "=r"(a) : "l"(p));
    return a;
}
__device__ __forceinline__ void cpa16(uint32_t s, const void* g) {
    asm volatile("cp.async.cg.shared.global [%0], [%1], 16;" :: "r"(s), "l"(g));
}
#define CP_COMMIT() asm volatile("cp.async.commit_group;" ::: "memory")
#define CP_WAIT0()  asm volatile("cp.async.wait_group 0;" ::: "memory")

__device__ __forceinline__ void ldmx4(uint32_t& r0, uint32_t& r1, uint32_t& r2,
                                      uint32_t& r3, uint32_t addr) {
    asm volatile("ldmatrix.sync.aligned.m8n8.x4.shared.b16 {%0,%1,%2,%3}, [%4];"
                 : "=r"(r0), "=r"(r1), "=r"(r2), "=r"(r3) : "r"(addr));
}
__device__ __forceinline__ void mma16816(float c[4], const uint32_t a[4],
                                         const uint32_t b[2]) {
    asm volatile(
        "mma.sync.aligned.m16n8k16.row.col.f32.bf16.bf16.f32 "
        "{%0,%1,%2,%3}, {%4,%5,%6,%7}, {%8,%9}, {%0,%1,%2,%3};"
        : "+f"(c[0]), "+f"(c[1]), "+f"(c[2]), "+f"(c[3])
        : "r"(a[0]), "r"(a[1]), "r"(a[2]), "r"(a[3]), "r"(b[0]), "r"(b[1]));
}

// smem tile: 128 rows x 32 bf16, pitch 40 elems (80B) -> 10240 B per tile
#define TPITCH 40
#define TBYTES 10240

// Core GEMM: acc[mt][nt][4] += A[128 x K] * B^T, both K-major, BK=32 double-buffered.
// smem must be 2*2*TBYTES = 40960 bytes.
__device__ __forceinline__ void gemm_core(
    const __nv_bfloat16* __restrict__ A, int lda,
    const __nv_bfloat16* __restrict__ B, int ldb,
    int nk, float acc[4][4][4], char* smem)
{
    const int tid = threadIdx.x;
    const int lane = tid & 31, wid = tid >> 5;
    const int wm = (wid >> 2) * 64, wn = (wid & 3) * 32;
    const uint32_t sbase = smem_u32(smem);

    // issue loads for chunk k0 into buffer buf
    auto issue = [&](int k0, int buf) {
        uint32_t sA = sbase + buf * 2 * TBYTES;
        uint32_t sB = sA + TBYTES;
        #pragma unroll
        for (int p = 0; p < 2; p++) {
            int idx = tid + p * 256;          // 0..511
            int row = idx >> 2, c = idx & 3;  // 4 x 16B per 64B row
            cpa16(sA + (row * TPITCH + c * 8) * 2,
                  A + (size_t)row * lda + k0 * 32 + c * 8);
            cpa16(sB + (row * TPITCH + c * 8) * 2,
                  B + (size_t)row * ldb + k0 * 32 + c * 8);
        }
        CP_COMMIT();
    };

    issue(0, 0);
    int buf = 0;
    for (int k0 = 0; k0 < nk; k0++) {
        CP_WAIT0();
        __syncthreads();
        if (k0 + 1 < nk) issue(k0 + 1, buf ^ 1);

        uint32_t sA = sbase + buf * 2 * TBYTES;
        uint32_t sB = sA + TBYTES;
        #pragma unroll
        for (int ks = 0; ks < 2; ks++) {
            uint32_t afr[4][4];
            #pragma unroll
            for (int mt = 0; mt < 4; mt++) {
                int row = wm + mt * 16 + (lane & 15);
                int col = ks * 16 + ((lane >> 4) & 1) * 8;
                ldmx4(afr[mt][0], afr[mt][1], afr[mt][2], afr[mt][3],
                      sA + (row * TPITCH + col) * 2);
            }
            uint32_t bfr[4][2];
            #pragma unroll
            for (int np = 0; np < 2; np++) {
                int row = wn + np * 16 + (lane & 7) + ((lane >> 4) & 1) * 8;
                int col = ks * 16 + ((lane >> 3) & 1) * 8;
                uint32_t r0, r1, r2, r3;
                ldmx4(r0, r1, r2, r3, sB + (row * TPITCH + col) * 2);
                bfr[np * 2][0] = r0; bfr[np * 2][1] = r1;
                bfr[np * 2 + 1][0] = r2; bfr[np * 2 + 1][1] = r3;
            }
            #pragma unroll
            for (int mt = 0; mt < 4; mt++)
                #pragma unroll
                for (int nt = 0; nt < 4; nt++)
                    mma16816(acc[mt][nt], afr[mt], bfr[nt]);
        }
        __syncthreads();
        buf ^= 1;
    }
}

// ---------------------------------------------------------------------------
// prep: convert weights to bf16 (stacked fg + h)
// ---------------------------------------------------------------------------
__global__ __launch_bounds__(256)
void conv_w_kernel(const float* __restrict__ fw, const float* __restrict__ gw,
                   const float* __restrict__ hw,
                   __nv_bfloat16* __restrict__ fgw, __nv_bfloat16* __restrict__ hwb)
{
    int i = blockIdx.x * 256 + threadIdx.x;
    if (i < 128 * CC) {
        float v = (i < 64 * CC) ? fw[i] : gw[i - 64 * CC];
        fgw[i] = __float2bfloat16(v);
    }
    int j = i - 128 * CC;
    if (j >= 0 && j < CC * CC) hwb[j] = __float2bfloat16(hw[j]);
}

// ---------------------------------------------------------------------------
// prep: transpose x [b][k][n] fp32 -> xT [b][n][k] bf16
// ---------------------------------------------------------------------------
__global__ __launch_bounds__(256)
void transpose_x_kernel(const float* __restrict__ x, __nv_bfloat16* __restrict__ xT)
{
    __shared__ float t[32][33];
    const int b = blockIdx.z;
    const int n0 = blockIdx.x * 32, k0 = blockIdx.y * 32;
    const float* xb = x + (size_t)b * CC * NN;
    for (int r = threadIdx.y; r < 32; r += 8)
        t[r][threadIdx.x] = xb[(size_t)(k0 + r) * NN + n0 + threadIdx.x];
    __syncthreads();
    __nv_bfloat16* xo = xT + (size_t)b * NN * CC;
    for (int r = threadIdx.y; r < 32; r += 8)
        xo[(size_t)(n0 + r) * CC + k0 + threadIdx.x] = __float2bfloat16(t[threadIdx.x][r]);
}

// ---------------------------------------------------------------------------
// fg projection: D[o(128 stacked)][n(128)] over K=512; write fT/gT [n][o] bf16
// ---------------------------------------------------------------------------
__global__ __launch_bounds__(256)
void fg_proj_mma(const __nv_bfloat16* __restrict__ fgw, const __nv_bfloat16* __restrict__ xT,
                 const float* __restrict__ f_b, const float* __restrict__ g_b,
                 __nv_bfloat16* __restrict__ fT, __nv_bfloat16* __restrict__ gT)
{
    __shared__ alignas(128) char smem[2 * 2 * TBYTES];
    const int b = blockIdx.z, n0 = blockIdx.x * 128;
    const int lane = threadIdx.x & 31, wid = threadIdx.x >> 5;
    const int wm = (wid >> 2) * 64, wn = (wid & 3) * 32;

    float acc[4][4][4] = {};
    gemm_core(fgw, CC, xT + (size_t)(b * NN + n0) * CC, CC, CC / 32, acc, smem);

    __nv_bfloat16* fTb = fT + (size_t)b * NN * OO;
    __nv_bfloat16* gTb = gT + (size_t)b * NN * OO;
    #pragma unroll
    for (int mt = 0; mt < 4; mt++) {
        #pragma unroll
        for (int half = 0; half < 2; half++) {
            int o = wm + mt * 16 + (lane >> 2) + half * 8;
            float bias = (o < 64) ? f_b[o] : g_b[o - 64];
            __nv_bfloat16* dst = (o < 64) ? (fTb + o) : (gTb + (o - 64));
            #pragma unroll
            for (int nt = 0; nt < 4; nt++) {
                int n = n0 + wn + nt * 8 + (lane & 3) * 2;
                dst[(size_t)n * OO]       = __float2bfloat16(acc[mt][nt][half * 2]     + bias);
                dst[(size_t)(n + 1) * OO] = __float2bfloat16(acc[mt][nt][half * 2 + 1] + bias);
            }
        }
    }
}

// ---------------------------------------------------------------------------
// h projection: D[c(128)][n(128)] over K=512; write hB [c][n] bf16
// ---------------------------------------------------------------------------
__global__ __launch_bounds__(256)
void h_proj_mma(const __nv_bfloat16* __restrict__ hwb, const __nv_bfloat16* __restrict__ xT,
                const float* __restrict__ h_b, __nv_bfloat16* __restrict__ hB)
{
    __shared__ alignas(128) char smem[2 * 2 * TBYTES];
    const int b = blockIdx.z, c0 = blockIdx.y * 128, n0 = blockIdx.x * 128;
    const int lane = threadIdx.x & 31, wid = threadIdx.x >> 5;
    const int wm = (wid >> 2) * 64, wn = (wid & 3) * 32;

    float acc[4][4][4] = {};
    gemm_core(hwb + (size_t)c0 * CC, CC,
              xT + (size_t)(b * NN + n0) * CC, CC, CC / 32, acc, smem);

    __nv_bfloat16* hb = hB + (size_t)b * CC * NN;
    #pragma unroll
    for (int mt = 0; mt < 4; mt++) {
        #pragma unroll
        for (int half = 0; half < 2; half++) {
            int c = c0 + wm + mt * 16 + (lane >> 2) + half * 8;
            float bias = h_b[c];
            #pragma unroll
            for (int nt = 0; nt < 4; nt++) {
                int n = n0 + wn + nt * 8 + (lane & 3) * 2;
                __nv_bfloat162 v;
                v.x = __float2bfloat16(acc[mt][nt][half * 2]     + bias);
                v.y = __float2bfloat16(acc[mt][nt][half * 2 + 1] + bias);
                *(__nv_bfloat162*)(hb + (size_t)c * NN + n) = v;
            }
        }
    }
}

// ---------------------------------------------------------------------------
// scores: D[i(128)][j(128)] = fT @ gT^T over K=64 -> fp32 scores
// ---------------------------------------------------------------------------
__global__ __launch_bounds__(256)
void scores_mma(const __nv_bfloat16* __restrict__ fT, const __nv_bfloat16* __restrict__ gT,
                float* __restrict__ scores)
{
    __shared__ alignas(128) char smem[2 * 2 * TBYTES];
    const int b = blockIdx.z, i0 = blockIdx.y * 128, j0 = blockIdx.x * 128;
    const int lane = threadIdx.x & 31, wid = threadIdx.x >> 5;
    const int wm = (wid >> 2) * 64, wn = (wid & 3) * 32;

    float acc[4][4][4] = {};
    gemm_core(fT + (size_t)(b * NN + i0) * OO, OO,
              gT + (size_t)(b * NN + j0) * OO, OO, OO / 32, acc, smem);

    float* sb = scores + (size_t)b * NN * NN;
    #pragma unroll
    for (int mt = 0; mt < 4; mt++) {
        #pragma unroll
        for (int half = 0; half < 2; half++) {
            int i = i0 + wm + mt * 16 + (lane >> 2) + half * 8;
            #pragma unroll
            for (int nt = 0; nt < 4; nt++) {
                int j = j0 + wn + nt * 8 + (lane & 3) * 2;
                float2 v = make_float2(acc[mt][nt][half * 2], acc[mt][nt][half * 2 + 1]);
                *(float2*)(sb + (size_t)i * NN + j) = v;
            }
        }
    }
}

// ---------------------------------------------------------------------------
// colstat: per (b,m) column max/sum over axis n (rows), coalesced across m
// ---------------------------------------------------------------------------
__global__ __launch_bounds__(256)
void colstat_kernel(const float* __restrict__ scores,
                    float* __restrict__ colmax, float* __restrict__ colinv)
{
    __shared__ float smax[8][128], ssum[8][128];
    const int b = blockIdx.y, m0 = blockIdx.x * 128;
    const int tid = threadIdx.x, r = tid >> 5, q = tid & 31;
    const float* s = scores + (size_t)b * NN * NN + m0 + q * 4;

    float mx0 = -3.4e38f, mx1 = -3.4e38f, mx2 = -3.4e38f, mx3 = -3.4e38f;
    float sm0 = 0.f, sm1 = 0.f, sm2 = 0.f, sm3 = 0.f;
    #pragma unroll 4
    for (int n = r; n < NN; n += 8) {
        float4 v = *(const float4*)(s + (size_t)n * NN);
        if (v.x > mx0) { sm0 = sm0 * __expf(mx0 - v.x) + 1.f; mx0 = v.x; } else sm0 += __expf(v.x - mx0);
        if (v.y > mx1) { sm1 = sm1 * __expf(mx1 - v.y) + 1.f; mx1 = v.y; } else sm1 += __expf(v.y - mx1);
        if (v.z > mx2) { sm2 = sm2 * __expf(mx2 - v.z) + 1.f; mx2 = v.z; } else sm2 += __expf(v.z - mx2);
        if (v.w > mx3) { sm3 = sm3 * __expf(mx3 - v.w) + 1.f; mx3 = v.w; } else sm3 += __expf(v.w - mx3);
    }
    smax[r][q * 4 + 0] = mx0; ssum[r][q * 4 + 0] = sm0;
    smax[r][q * 4 + 1] = mx1; ssum[r][q * 4 + 1] = sm1;
    smax[r][q * 4 + 2] = mx2; ssum[r][q * 4 + 2] = sm2;
    smax[r][q * 4 + 3] = mx3; ssum[r][q * 4 + 3] = sm3;
    __syncthreads();
    if (tid < 128) {
        float M = -3.4e38f, S = 0.f;
        #pragma unroll
        for (int g = 0; g < 8; g++) {
            float mg = smax[g][tid], sg = ssum[g][tid];
            if (mg > M) { S = S * __expf(M - mg) + sg; M = mg; }
            else        { S += sg * __expf(mg - M); }
        }
        colmax[b * NN + m0 + tid] = M;
        colinv[b * NN + m0 + tid] = 1.0f / S;
    }
}

// ---------------------------------------------------------------------------
// probT: probT[b][m][n] = exp(scores[n][m]-max[m])*inv[m], bf16, 64x64 transpose
// ---------------------------------------------------------------------------
__global__ __launch_bounds__(256)
void probT_kernel(const float* __restrict__ scores, const float* __restrict__ colmax,
                  const float* __restrict__ colinv, __nv_bfloat16* __restrict__ probT)
{
    __shared__ __nv_bfloat16 ts[64][72];
    __shared__ float smax[64], sinv[64];
    const int b = blockIdx.z, n0 = blockIdx.y * 64, m0 = blockIdx.x * 64;
    const int tid = threadIdx.x;
    if (tid < 64) { smax[tid] = colmax[b * NN + m0 + tid];
                    sinv[tid] = colinv[b * NN + m0 + tid]; }
    __syncthreads();

    const int rr = tid >> 4, cc = (tid & 15) * 4;
    const float* sb = scores + (size_t)b * NN * NN;
    #pragma unroll
    for (int p = 0; p < 4; p++) {
        int n = n0 + rr + p * 16;
        float4 v = *(const float4*)(sb + (size_t)n * NN + m0 + cc);
        ts[cc + 0][rr + p * 16] = __float2bfloat16(__expf(v.x - smax[cc + 0]) * sinv[cc + 0]);
        ts[cc + 1][rr + p * 16] = __float2bfloat16(__expf(v.y - smax[cc + 1]) * sinv[cc + 1]);
        ts[cc + 2][rr + p * 16] = __float2bfloat16(__expf(v.z - smax[cc + 2]) * sinv[cc + 2]);
        ts[cc + 3][rr + p * 16] = __float2bfloat16(__expf(v.w - smax[cc + 3]) * sinv[cc + 3]);
    }
    __syncthreads();

    const int mr = tid >> 2, sg = (tid & 3) * 16;
    __nv_bfloat16* pb = probT + (size_t)b * NN * NN + (size_t)(m0 + mr) * NN + n0 + sg;
    uint4 a0 = *(const uint4*)&ts[mr][sg];
    uint4 a1 = *(const uint4*)&ts[mr][sg + 8];
    *(uint4*)pb = a0;
    *(uint4*)(pb + 8) = a1;
}

// ---------------------------------------------------------------------------
// attn: D[c(128)][m(128)] = sum_n hB[c][n]*probT[m][n] over K=4096
// epilogue: out = gamma*D + x
// ---------------------------------------------------------------------------
__global__ __launch_bounds__(256)
void attn_mma(const __nv_bfloat16* __restrict__ hB, const __nv_bfloat16* __restrict__ probT,
              const float* __restrict__ x, const float* __restrict__ gamma_p,
              float* __restrict__ out)
{
    __shared__ alignas(128) char smem[2 * 2 * TBYTES];
    const int b = blockIdx.z, c0 = blockIdx.y * 128, m0 = blockIdx.x * 128;
    const int lane = threadIdx.x & 31, wid = threadIdx.x >> 5;
    const int wm = (wid >> 2) * 64, wn = (wid & 3) * 32;

    float acc[4][4][4] = {};
    gemm_core(hB + ((size_t)b * CC + c0) * NN, NN,
              probT + ((size_t)b * NN + m0) * NN, NN, NN / 32, acc, smem);

    const float gamma = *gamma_p;
    #pragma unroll
    for (int mt = 0; mt < 4; mt++) {
        #pragma unroll
        for (int half = 0; half < 2; half++) {
            int c = c0 + wm + mt * 16 + (lane >> 2) + half * 8;
            size_t rowb = ((size_t)b * CC + c) * NN;
            #pragma unroll
            for (int nt = 0; nt < 4; nt++) {
                int m = m0 + wn + nt * 8 + (lane & 3) * 2;
                float2 xv = *(const float2*)(x + rowb + m);
                float2 ov;
                ov.x = gamma * acc[mt][nt][half * 2]     + xv.x;
                ov.y = gamma * acc[mt][nt][half * 2 + 1] + xv.y;
                *(float2*)(out + rowb + m) = ov;
            }
        }
    }
}

// ---------------------------------------------------------------------------
extern "C" void kernel_launch(void* const* d_in, const int* in_sizes, int n_in,
                              void* d_out, int out_size)
{
    const float* x     = (const float*)d_in[0];
    const float* f_w   = (const float*)d_in[1];
    const float* f_b   = (const float*)d_in[2];
    const float* g_w   = (const float*)d_in[3];
    const float* g_b   = (const float*)d_in[4];
    const float* h_w   = (const float*)d_in[5];
    const float* h_b   = (const float*)d_in[6];
    const float* gamma = (const float*)d_in[7];
    float* out = (float*)d_out;

    __nv_bfloat16 *pxT, *pfgw, *phw, *pfT, *pgT, *phB, *pprobT;
    float *ps, *pmax, *pinv;
    cudaGetSymbolAddress((void**)&pxT,   d_xT);
    cudaGetSymbolAddress((void**)&pfgw,  d_fgw);
    cudaGetSymbolAddress((void**)&phw,   d_hw);
    cudaGetSymbolAddress((void**)&pfT,   d_fT);
    cudaGetSymbolAddress((void**)&pgT,   d_gT);
    cudaGetSymbolAddress((void**)&phB,   d_hB);
    cudaGetSymbolAddress((void**)&ps,    d_scores);
    cudaGetSymbolAddress((void**)&pmax,  d_colmax);
    cudaGetSymbolAddress((void**)&pinv,  d_colinv);
    cudaGetSymbolAddress((void**)&pprobT, d_probT);

    // prep
    conv_w_kernel<<<1280, 256>>>(f_w, g_w, h_w, pfgw, phw);
    transpose_x_kernel<<<dim3(NN / 32, CC / 32, BATCH), dim3(32, 8)>>>(x, pxT);

    // projections (mma.sync)
    fg_proj_mma<<<dim3(NN / 128, 1, BATCH), 256>>>(pfgw, pxT, f_b, g_b, pfT, pgT);
    h_proj_mma <<<dim3(NN / 128, CC / 128, BATCH), 256>>>(phw, pxT, h_b, phB);

    // scores (mma.sync)
    scores_mma<<<dim3(NN / 128, NN / 128, BATCH), 256>>>(pfT, pgT, ps);

    // softmax stats + transposed bf16 probs
    colstat_kernel<<<dim3(NN / 128, BATCH), 256>>>(ps, pmax, pinv);
    probT_kernel<<<dim3(NN / 64, NN / 64, BATCH), 256>>>(ps, pmax, pinv, pprobT);

    // attention GEMM + epilogue (mma.sync)
    attn_mma<<<dim3(NN / 128, CC / 128, BATCH), 256>>>(phB, pprobT, x, gamma, out);
}

// round 5
// speedup vs baseline: 4.9099x; 1.0389x over previous
#include <cuda_runtime.h>
#include <cuda_bf16.h>
#include <cstdint>
#include <cstddef>

#define BATCH 4
#define CC    512
#define OO    64
#define NN    4096

// ---------------- scratch (device globals; allocation-free) ----------------
__device__ __nv_bfloat16 d_xT [BATCH * NN * CC];      // x transposed [b][n][k] bf16
__device__ __nv_bfloat16 d_fgw[128 * CC];             // stacked [f_w; g_w] bf16
__device__ __nv_bfloat16 d_hw [CC * CC];              // h_w bf16
__device__ __nv_bfloat16 d_fT [BATCH * NN * OO];      // f transposed [b][i][o]
__device__ __nv_bfloat16 d_gT [BATCH * NN * OO];      // g transposed [b][j][o]
__device__ __nv_bfloat16 d_hB [BATCH * CC * NN];      // h bf16 [b][c][n]
__device__ float d_scores[(size_t)BATCH * NN * NN];   // fp32 scores [b][i][j]
__device__ float d_colmax[BATCH * NN];
__device__ float d_colinv[BATCH * NN];
__device__ __nv_bfloat16 d_probT[(size_t)BATCH * NN * NN]; // probs^T [b][m][n] bf16

// ------------------------- helpers -----------------------------------------
__device__ __forceinline__ uint32_t smem_u32(const void* p) {
    uint32_t a;
    asm("{ .reg .u64 t; cvta.to.shared.u64 t, %1; cvt.u32.u64 %0, t; }"
        : "=r"(a) : "l"(p));
    return a;
}
__device__ __forceinline__ void cpa16(uint32_t s, const void* g) {
    asm volatile("cp.async.cg.shared.global [%0], [%1], 16;" :: "r"(s), "l"(g));
}
#define CP_COMMIT() asm volatile("cp.async.commit_group;" ::: "memory")
#define CP_WAIT1()  asm volatile("cp.async.wait_group 1;" ::: "memory")

__device__ __forceinline__ void ldmx4(uint32_t& r0, uint32_t& r1, uint32_t& r2,
                                      uint32_t& r3, uint32_t addr) {
    asm volatile("ldmatrix.sync.aligned.m8n8.x4.shared.b16 {%0,%1,%2,%3}, [%4];"
                 : "=r"(r0), "=r"(r1), "=r"(r2), "=r"(r3) : "r"(addr));
}
__device__ __forceinline__ void mma16816(float c[4], const uint32_t a[4],
                                         const uint32_t b[2]) {
    asm volatile(
        "mma.sync.aligned.m16n8k16.row.col.f32.bf16.bf16.f32 "
        "{%0,%1,%2,%3}, {%4,%5,%6,%7}, {%8,%9}, {%0,%1,%2,%3};"
        : "+f"(c[0]), "+f"(c[1]), "+f"(c[2]), "+f"(c[3])
        : "r"(a[0]), "r"(a[1]), "r"(a[2]), "r"(a[3]), "r"(b[0]), "r"(b[1]));
}

// smem tile: 128 rows x 32 bf16, pitch 40 elems (80B) -> 10240 B per operand
#define TPITCH 40
#define TBYTES 10240
#define NSTAGE 3
#define STAGE_BYTES (2 * TBYTES)
#define SMEM_DYN (NSTAGE * STAGE_BYTES)   // 61440

// Core GEMM: acc[mt][nt][4] += A[128 x K] * B^T, both K-major, BK=32.
// 3-stage cp.async circular pipeline, ONE __syncthreads per chunk.
__device__ __forceinline__ void gemm_core(
    const __nv_bfloat16* __restrict__ A, int lda,
    const __nv_bfloat16* __restrict__ B, int ldb,
    int nk, float acc[4][4][4], char* smem)
{
    const int tid = threadIdx.x;
    const int lane = tid & 31, wid = tid >> 5;
    const int wm = (wid >> 2) * 64, wn = (wid & 3) * 32;
    const uint32_t sbase = smem_u32(smem);

    // issue stage st (empty commit group past the end keeps arithmetic uniform)
    auto issue = [&](int st) {
        if (st < nk) {
            uint32_t sA = sbase + (st % NSTAGE) * STAGE_BYTES;
            uint32_t sB = sA + TBYTES;
            #pragma unroll
            for (int p = 0; p < 2; p++) {
                int idx = tid + p * 256;          // 0..511
                int row = idx >> 2, c = idx & 3;  // 4 x 16B per 64B row
                cpa16(sA + (row * TPITCH + c * 8) * 2,
                      A + (size_t)row * lda + st * 32 + c * 8);
                cpa16(sB + (row * TPITCH + c * 8) * 2,
                      B + (size_t)row * ldb + st * 32 + c * 8);
            }
        }
        CP_COMMIT();
    };

    issue(0); issue(1);
    for (int k0 = 0; k0 < nk; k0++) {
        CP_WAIT1();            // stage k0 complete (all but newest group)
        __syncthreads();       // also: everyone done reading stage k0-1
        issue(k0 + 2);         // writes buf (k0+2)%3 == (k0-1)%3 — safe post-sync

        uint32_t sA = sbase + (k0 % NSTAGE) * STAGE_BYTES;
        uint32_t sB = sA + TBYTES;
        #pragma unroll
        for (int ks = 0; ks < 2; ks++) {
            uint32_t afr[4][4];
            #pragma unroll
            for (int mt = 0; mt < 4; mt++) {
                int row = wm + mt * 16 + (lane & 15);
                int col = ks * 16 + ((lane >> 4) & 1) * 8;
                ldmx4(afr[mt][0], afr[mt][1], afr[mt][2], afr[mt][3],
                      sA + (row * TPITCH + col) * 2);
            }
            uint32_t bfr[4][2];
            #pragma unroll
            for (int np = 0; np < 2; np++) {
                int row = wn + np * 16 + (lane & 7) + ((lane >> 4) & 1) * 8;
                int col = ks * 16 + ((lane >> 3) & 1) * 8;
                uint32_t r0, r1, r2, r3;
                ldmx4(r0, r1, r2, r3, sB + (row * TPITCH + col) * 2);
                bfr[np * 2][0] = r0; bfr[np * 2][1] = r1;
                bfr[np * 2 + 1][0] = r2; bfr[np * 2 + 1][1] = r3;
            }
            #pragma unroll
            for (int mt = 0; mt < 4; mt++)
                #pragma unroll
                for (int nt = 0; nt < 4; nt++)
                    mma16816(acc[mt][nt], afr[mt], bfr[nt]);
        }
    }
}

// ---------------------------------------------------------------------------
// prep: convert weights to bf16 (stacked fg + h)
// ---------------------------------------------------------------------------
__global__ __launch_bounds__(256)
void conv_w_kernel(const float* __restrict__ fw, const float* __restrict__ gw,
                   const float* __restrict__ hw,
                   __nv_bfloat16* __restrict__ fgw, __nv_bfloat16* __restrict__ hwb)
{
    int i = blockIdx.x * 256 + threadIdx.x;
    if (i < 128 * CC) {
        float v = (i < 64 * CC) ? fw[i] : gw[i - 64 * CC];
        fgw[i] = __float2bfloat16(v);
    }
    int j = i - 128 * CC;
    if (j >= 0 && j < CC * CC) hwb[j] = __float2bfloat16(hw[j]);
}

// ---------------------------------------------------------------------------
// prep: transpose x [b][k][n] fp32 -> xT [b][n][k] bf16
// ---------------------------------------------------------------------------
__global__ __launch_bounds__(256)
void transpose_x_kernel(const float* __restrict__ x, __nv_bfloat16* __restrict__ xT)
{
    __shared__ float t[32][33];
    const int b = blockIdx.z;
    const int n0 = blockIdx.x * 32, k0 = blockIdx.y * 32;
    const float* xb = x + (size_t)b * CC * NN;
    for (int r = threadIdx.y; r < 32; r += 8)
        t[r][threadIdx.x] = xb[(size_t)(k0 + r) * NN + n0 + threadIdx.x];
    __syncthreads();
    __nv_bfloat16* xo = xT + (size_t)b * NN * CC;
    for (int r = threadIdx.y; r < 32; r += 8)
        xo[(size_t)(n0 + r) * CC + k0 + threadIdx.x] = __float2bfloat16(t[threadIdx.x][r]);
}

// ---------------------------------------------------------------------------
// fg projection: D[o(128 stacked)][n(128)] over K=512; write fT/gT [n][o] bf16
// ---------------------------------------------------------------------------
__global__ __launch_bounds__(256)
void fg_proj_mma(const __nv_bfloat16* __restrict__ fgw, const __nv_bfloat16* __restrict__ xT,
                 const float* __restrict__ f_b, const float* __restrict__ g_b,
                 __nv_bfloat16* __restrict__ fT, __nv_bfloat16* __restrict__ gT)
{
    extern __shared__ char dsm[];
    const int b = blockIdx.z, n0 = blockIdx.x * 128;
    const int lane = threadIdx.x & 31, wid = threadIdx.x >> 5;
    const int wm = (wid >> 2) * 64, wn = (wid & 3) * 32;

    float acc[4][4][4] = {};
    gemm_core(fgw, CC, xT + (size_t)(b * NN + n0) * CC, CC, CC / 32, acc, dsm);

    __nv_bfloat16* fTb = fT + (size_t)b * NN * OO;
    __nv_bfloat16* gTb = gT + (size_t)b * NN * OO;
    #pragma unroll
    for (int mt = 0; mt < 4; mt++) {
        #pragma unroll
        for (int half = 0; half < 2; half++) {
            int o = wm + mt * 16 + (lane >> 2) + half * 8;
            float bias = (o < 64) ? f_b[o] : g_b[o - 64];
            __nv_bfloat16* dst = (o < 64) ? (fTb + o) : (gTb + (o - 64));
            #pragma unroll
            for (int nt = 0; nt < 4; nt++) {
                int n = n0 + wn + nt * 8 + (lane & 3) * 2;
                dst[(size_t)n * OO]       = __float2bfloat16(acc[mt][nt][half * 2]     + bias);
                dst[(size_t)(n + 1) * OO] = __float2bfloat16(acc[mt][nt][half * 2 + 1] + bias);
            }
        }
    }
}

// ---------------------------------------------------------------------------
// h projection: D[c(128)][n(128)] over K=512; write hB [c][n] bf16
// ---------------------------------------------------------------------------
__global__ __launch_bounds__(256)
void h_proj_mma(const __nv_bfloat16* __restrict__ hwb, const __nv_bfloat16* __restrict__ xT,
                const float* __restrict__ h_b, __nv_bfloat16* __restrict__ hB)
{
    extern __shared__ char dsm[];
    const int b = blockIdx.z, c0 = blockIdx.y * 128, n0 = blockIdx.x * 128;
    const int lane = threadIdx.x & 31, wid = threadIdx.x >> 5;
    const int wm = (wid >> 2) * 64, wn = (wid & 3) * 32;

    float acc[4][4][4] = {};
    gemm_core(hwb + (size_t)c0 * CC, CC,
              xT + (size_t)(b * NN + n0) * CC, CC, CC / 32, acc, dsm);

    __nv_bfloat16* hb = hB + (size_t)b * CC * NN;
    #pragma unroll
    for (int mt = 0; mt < 4; mt++) {
        #pragma unroll
        for (int half = 0; half < 2; half++) {
            int c = c0 + wm + mt * 16 + (lane >> 2) + half * 8;
            float bias = h_b[c];
            #pragma unroll
            for (int nt = 0; nt < 4; nt++) {
                int n = n0 + wn + nt * 8 + (lane & 3) * 2;
                __nv_bfloat162 v;
                v.x = __float2bfloat16(acc[mt][nt][half * 2]     + bias);
                v.y = __float2bfloat16(acc[mt][nt][half * 2 + 1] + bias);
                *(__nv_bfloat162*)(hb + (size_t)c * NN + n) = v;
            }
        }
    }
}

// ---------------------------------------------------------------------------
// scores: D[i(128)][j(128)] = fT @ gT^T over K=64 -> fp32 scores
// ---------------------------------------------------------------------------
__global__ __launch_bounds__(256)
void scores_mma(const __nv_bfloat16* __restrict__ fT, const __nv_bfloat16* __restrict__ gT,
                float* __restrict__ scores)
{
    extern __shared__ char dsm[];
    const int b = blockIdx.z, i0 = blockIdx.y * 128, j0 = blockIdx.x * 128;
    const int lane = threadIdx.x & 31, wid = threadIdx.x >> 5;
    const int wm = (wid >> 2) * 64, wn = (wid & 3) * 32;

    float acc[4][4][4] = {};
    gemm_core(fT + (size_t)(b * NN + i0) * OO, OO,
              gT + (size_t)(b * NN + j0) * OO, OO, OO / 32, acc, dsm);

    float* sb = scores + (size_t)b * NN * NN;
    #pragma unroll
    for (int mt = 0; mt < 4; mt++) {
        #pragma unroll
        for (int half = 0; half < 2; half++) {
            int i = i0 + wm + mt * 16 + (lane >> 2) + half * 8;
            #pragma unroll
            for (int nt = 0; nt < 4; nt++) {
                int j = j0 + wn + nt * 8 + (lane & 3) * 2;
                float2 v = make_float2(acc[mt][nt][half * 2], acc[mt][nt][half * 2 + 1]);
                *(float2*)(sb + (size_t)i * NN + j) = v;
            }
        }
    }
}

// ---------------------------------------------------------------------------
// colstat: per (b,m) column max/sum over axis n (rows), coalesced across m
// ---------------------------------------------------------------------------
__global__ __launch_bounds__(256)
void colstat_kernel(const float* __restrict__ scores,
                    float* __restrict__ colmax, float* __restrict__ colinv)
{
    __shared__ float smax[8][128], ssum[8][128];
    const int b = blockIdx.y, m0 = blockIdx.x * 128;
    const int tid = threadIdx.x, r = tid >> 5, q = tid & 31;
    const float* s = scores + (size_t)b * NN * NN + m0 + q * 4;

    float mx0 = -3.4e38f, mx1 = -3.4e38f, mx2 = -3.4e38f, mx3 = -3.4e38f;
    float sm0 = 0.f, sm1 = 0.f, sm2 = 0.f, sm3 = 0.f;
    #pragma unroll 4
    for (int n = r; n < NN; n += 8) {
        float4 v = *(const float4*)(s + (size_t)n * NN);
        if (v.x > mx0) { sm0 = sm0 * __expf(mx0 - v.x) + 1.f; mx0 = v.x; } else sm0 += __expf(v.x - mx0);
        if (v.y > mx1) { sm1 = sm1 * __expf(mx1 - v.y) + 1.f; mx1 = v.y; } else sm1 += __expf(v.y - mx1);
        if (v.z > mx2) { sm2 = sm2 * __expf(mx2 - v.z) + 1.f; mx2 = v.z; } else sm2 += __expf(v.z - mx2);
        if (v.w > mx3) { sm3 = sm3 * __expf(mx3 - v.w) + 1.f; mx3 = v.w; } else sm3 += __expf(v.w - mx3);
    }
    smax[r][q * 4 + 0] = mx0; ssum[r][q * 4 + 0] = sm0;
    smax[r][q * 4 + 1] = mx1; ssum[r][q * 4 + 1] = sm1;
    smax[r][q * 4 + 2] = mx2; ssum[r][q * 4 + 2] = sm2;
    smax[r][q * 4 + 3] = mx3; ssum[r][q * 4 + 3] = sm3;
    __syncthreads();
    if (tid < 128) {
        float M = -3.4e38f, S = 0.f;
        #pragma unroll
        for (int g = 0; g < 8; g++) {
            float mg = smax[g][tid], sg = ssum[g][tid];
            if (mg > M) { S = S * __expf(M - mg) + sg; M = mg; }
            else        { S += sg * __expf(mg - M); }
        }
        colmax[b * NN + m0 + tid] = M;
        colinv[b * NN + m0 + tid] = 1.0f / S;
    }
}

// ---------------------------------------------------------------------------
// probT: probT[b][m][n] = exp(scores[n][m]-max[m])*inv[m], bf16, 64x64 transpose
// ---------------------------------------------------------------------------
__global__ __launch_bounds__(256)
void probT_kernel(const float* __restrict__ scores, const float* __restrict__ colmax,
                  const float* __restrict__ colinv, __nv_bfloat16* __restrict__ probT)
{
    __shared__ __nv_bfloat16 ts[64][72];
    __shared__ float smax[64], sinv[64];
    const int b = blockIdx.z, n0 = blockIdx.y * 64, m0 = blockIdx.x * 64;
    const int tid = threadIdx.x;
    if (tid < 64) { smax[tid] = colmax[b * NN + m0 + tid];
                    sinv[tid] = colinv[b * NN + m0 + tid]; }
    __syncthreads();

    const int rr = tid >> 4, cc = (tid & 15) * 4;
    const float* sb = scores + (size_t)b * NN * NN;
    #pragma unroll
    for (int p = 0; p < 4; p++) {
        int n = n0 + rr + p * 16;
        float4 v = *(const float4*)(sb + (size_t)n * NN + m0 + cc);
        ts[cc + 0][rr + p * 16] = __float2bfloat16(__expf(v.x - smax[cc + 0]) * sinv[cc + 0]);
        ts[cc + 1][rr + p * 16] = __float2bfloat16(__expf(v.y - smax[cc + 1]) * sinv[cc + 1]);
        ts[cc + 2][rr + p * 16] = __float2bfloat16(__expf(v.z - smax[cc + 2]) * sinv[cc + 2]);
        ts[cc + 3][rr + p * 16] = __float2bfloat16(__expf(v.w - smax[cc + 3]) * sinv[cc + 3]);
    }
    __syncthreads();

    const int mr = tid >> 2, sg = (tid & 3) * 16;
    __nv_bfloat16* pb = probT + (size_t)b * NN * NN + (size_t)(m0 + mr) * NN + n0 + sg;
    uint4 a0 = *(const uint4*)&ts[mr][sg];
    uint4 a1 = *(const uint4*)&ts[mr][sg + 8];
    *(uint4*)pb = a0;
    *(uint4*)(pb + 8) = a1;
}

// ---------------------------------------------------------------------------
// attn: D[c(128)][m(128)] = sum_n hB[c][n]*probT[m][n] over K=4096
// epilogue: out = gamma*D + x
// ---------------------------------------------------------------------------
__global__ __launch_bounds__(256)
void attn_mma(const __nv_bfloat16* __restrict__ hB, const __nv_bfloat16* __restrict__ probT,
              const float* __restrict__ x, const float* __restrict__ gamma_p,
              float* __restrict__ out)
{
    extern __shared__ char dsm[];
    const int b = blockIdx.z, c0 = blockIdx.y * 128, m0 = blockIdx.x * 128;
    const int lane = threadIdx.x & 31, wid = threadIdx.x >> 5;
    const int wm = (wid >> 2) * 64, wn = (wid & 3) * 32;

    float acc[4][4][4] = {};
    gemm_core(hB + ((size_t)b * CC + c0) * NN, NN,
              probT + ((size_t)b * NN + m0) * NN, NN, NN / 32, acc, dsm);

    const float gamma = *gamma_p;
    #pragma unroll
    for (int mt = 0; mt < 4; mt++) {
        #pragma unroll
        for (int half = 0; half < 2; half++) {
            int c = c0 + wm + mt * 16 + (lane >> 2) + half * 8;
            size_t rowb = ((size_t)b * CC + c) * NN;
            #pragma unroll
            for (int nt = 0; nt < 4; nt++) {
                int m = m0 + wn + nt * 8 + (lane & 3) * 2;
                float2 xv = *(const float2*)(x + rowb + m);
                float2 ov;
                ov.x = gamma * acc[mt][nt][half * 2]     + xv.x;
                ov.y = gamma * acc[mt][nt][half * 2 + 1] + xv.y;
                *(float2*)(out + rowb + m) = ov;
            }
        }
    }
}

// ---------------------------------------------------------------------------
extern "C" void kernel_launch(void* const* d_in, const int* in_sizes, int n_in,
                              void* d_out, int out_size)
{
    const float* x     = (const float*)d_in[0];
    const float* f_w   = (const float*)d_in[1];
    const float* f_b   = (const float*)d_in[2];
    const float* g_w   = (const float*)d_in[3];
    const float* g_b   = (const float*)d_in[4];
    const float* h_w   = (const float*)d_in[5];
    const float* h_b   = (const float*)d_in[6];
    const float* gamma = (const float*)d_in[7];
    float* out = (float*)d_out;

    __nv_bfloat16 *pxT, *pfgw, *phw, *pfT, *pgT, *phB, *pprobT;
    float *ps, *pmax, *pinv;
    cudaGetSymbolAddress((void**)&pxT,   d_xT);
    cudaGetSymbolAddress((void**)&pfgw,  d_fgw);
    cudaGetSymbolAddress((void**)&phw,   d_hw);
    cudaGetSymbolAddress((void**)&pfT,   d_fT);
    cudaGetSymbolAddress((void**)&pgT,   d_gT);
    cudaGetSymbolAddress((void**)&phB,   d_hB);
    cudaGetSymbolAddress((void**)&ps,    d_scores);
    cudaGetSymbolAddress((void**)&pmax,  d_colmax);
    cudaGetSymbolAddress((void**)&pinv,  d_colinv);
    cudaGetSymbolAddress((void**)&pprobT, d_probT);

    // unconditional every call — deterministic, no static guards
    cudaFuncSetAttribute(fg_proj_mma, cudaFuncAttributeMaxDynamicSharedMemorySize, SMEM_DYN);
    cudaFuncSetAttribute(h_proj_mma,  cudaFuncAttributeMaxDynamicSharedMemorySize, SMEM_DYN);
    cudaFuncSetAttribute(scores_mma,  cudaFuncAttributeMaxDynamicSharedMemorySize, SMEM_DYN);
    cudaFuncSetAttribute(attn_mma,    cudaFuncAttributeMaxDynamicSharedMemorySize, SMEM_DYN);

    // prep
    conv_w_kernel<<<1280, 256>>>(f_w, g_w, h_w, pfgw, phw);
    transpose_x_kernel<<<dim3(NN / 32, CC / 32, BATCH), dim3(32, 8)>>>(x, pxT);

    // projections (mma.sync)
    fg_proj_mma<<<dim3(NN / 128, 1, BATCH), 256, SMEM_DYN>>>(pfgw, pxT, f_b, g_b, pfT, pgT);
    h_proj_mma <<<dim3(NN / 128, CC / 128, BATCH), 256, SMEM_DYN>>>(phw, pxT, h_b, phB);

    // scores (mma.sync)
    scores_mma<<<dim3(NN / 128, NN / 128, BATCH), 256, SMEM_DYN>>>(pfT, pgT, ps);

    // softmax stats + transposed bf16 probs
    colstat_kernel<<<dim3(NN / 128, BATCH), 256>>>(ps, pmax, pinv);
    probT_kernel<<<dim3(NN / 64, NN / 64, BATCH), 256>>>(ps, pmax, pinv, pprobT);

    // attention GEMM + epilogue (mma.sync)
    attn_mma<<<dim3(NN / 128, CC / 128, BATCH), 256, SMEM_DYN>>>(phB, pprobT, x, gamma, out);
}

// round 8
// speedup vs baseline: 10.2581x; 2.0893x over previous
#include <cuda_runtime.h>
#include <cuda_bf16.h>
#include <cstdint>
#include <cstddef>

#define BATCH 4
#define CC    512
#define OO    64
#define NN    4096

// ---------------- scratch (device globals; allocation-free) ----------------
__device__ __nv_bfloat16 d_xT [BATCH * NN * CC];      // x transposed [b][n][k] bf16
__device__ __nv_bfloat16 d_fgw[128 * CC];             // stacked [f_w; g_w] bf16
__device__ __nv_bfloat16 d_hw [CC * CC];              // h_w bf16
__device__ __nv_bfloat16 d_fT [BATCH * NN * OO];      // f transposed [b][i][o]
__device__ __nv_bfloat16 d_gT [BATCH * NN * OO];      // g transposed [b][j][o]
__device__ __nv_bfloat16 d_hB [BATCH * CC * NN];      // h bf16 [b][c][n]
__device__ __nv_bfloat16 d_eT [(size_t)BATCH * NN * NN]; // exp(scores)^T [b][m][n] bf16
__device__ float d_colsum[BATCH * NN];                // sum_n exp(scores[n][m])

// ------------------------- helpers -----------------------------------------
__device__ __forceinline__ uint32_t smem_u32(const void* p) {
    uint32_t a;
    asm("{ .reg .u64 t; cvta.to.shared.u64 t, %1; cvt.u32.u64 %0, t; }"
        : "=r"(a) : "l"(p));
    return a;
}
__device__ __forceinline__ void cpa16(uint32_t s, const void* g) {
    asm volatile("cp.async.cg.shared.global [%0], [%1], 16;" :: "r"(s), "l"(g));
}
#define CP_COMMIT() asm volatile("cp.async.commit_group;" ::: "memory")
#define CP_WAIT1()  asm volatile("cp.async.wait_group 1;" ::: "memory")

__device__ __forceinline__ void ldmx4(uint32_t& r0, uint32_t& r1, uint32_t& r2,
                                      uint32_t& r3, uint32_t addr) {
    asm volatile("ldmatrix.sync.aligned.m8n8.x4.shared.b16 {%0,%1,%2,%3}, [%4];"
                 : "=r"(r0), "=r"(r1), "=r"(r2), "=r"(r3) : "r"(addr));
}
__device__ __forceinline__ void mma16816(float c[4], const uint32_t a[4],
                                         const uint32_t b[2]) {
    asm volatile(
        "mma.sync.aligned.m16n8k16.row.col.f32.bf16.bf16.f32 "
        "{%0,%1,%2,%3}, {%4,%5,%6,%7}, {%8,%9}, {%0,%1,%2,%3};"
        : "+f"(c[0]), "+f"(c[1]), "+f"(c[2]), "+f"(c[3])
        : "r"(a[0]), "r"(a[1]), "r"(a[2]), "r"(a[3]), "r"(b[0]), "r"(b[1]));
}

// smem tile: 128 rows x 32 bf16, pitch 40 elems (80B) -> 10240 B per operand
#define TPITCH 40
#define TBYTES 10240
#define NSTAGE 3
#define STAGE_BYTES (2 * TBYTES)
#define SMEM_DYN (NSTAGE * STAGE_BYTES)   // 61440 (also covers 128x136 bf16 transpose = 34816)

// Core GEMM: acc[mt][nt][4] += A[128 x K] * B^T, both K-major, BK=32.
// 3-stage cp.async circular pipeline, ONE __syncthreads per chunk.
__device__ __forceinline__ void gemm_core(
    const __nv_bfloat16* __restrict__ A, int lda,
    const __nv_bfloat16* __restrict__ B, int ldb,
    int nk, float acc[4][4][4], char* smem)
{
    const int tid = threadIdx.x;
    const int lane = tid & 31, wid = tid >> 5;
    const int wm = (wid >> 2) * 64, wn = (wid & 3) * 32;
    const uint32_t sbase = smem_u32(smem);

    auto issue = [&](int st) {
        if (st < nk) {
            uint32_t sA = sbase + (st % NSTAGE) * STAGE_BYTES;
            uint32_t sB = sA + TBYTES;
            #pragma unroll
            for (int p = 0; p < 2; p++) {
                int idx = tid + p * 256;
                int row = idx >> 2, c = idx & 3;
                cpa16(sA + (row * TPITCH + c * 8) * 2,
                      A + (size_t)row * lda + st * 32 + c * 8);
                cpa16(sB + (row * TPITCH + c * 8) * 2,
                      B + (size_t)row * ldb + st * 32 + c * 8);
            }
        }
        CP_COMMIT();
    };

    issue(0); issue(1);
    for (int k0 = 0; k0 < nk; k0++) {
        CP_WAIT1();
        __syncthreads();
        issue(k0 + 2);

        uint32_t sA = sbase + (k0 % NSTAGE) * STAGE_BYTES;
        uint32_t sB = sA + TBYTES;
        #pragma unroll
        for (int ks = 0; ks < 2; ks++) {
            uint32_t afr[4][4];
            #pragma unroll
            for (int mt = 0; mt < 4; mt++) {
                int row = wm + mt * 16 + (lane & 15);
                int col = ks * 16 + ((lane >> 4) & 1) * 8;
                ldmx4(afr[mt][0], afr[mt][1], afr[mt][2], afr[mt][3],
                      sA + (row * TPITCH + col) * 2);
            }
            uint32_t bfr[4][2];
            #pragma unroll
            for (int np = 0; np < 2; np++) {
                int row = wn + np * 16 + (lane & 7) + ((lane >> 4) & 1) * 8;
                int col = ks * 16 + ((lane >> 3) & 1) * 8;
                uint32_t r0, r1, r2, r3;
                ldmx4(r0, r1, r2, r3, sB + (row * TPITCH + col) * 2);
                bfr[np * 2][0] = r0; bfr[np * 2][1] = r1;
                bfr[np * 2 + 1][0] = r2; bfr[np * 2 + 1][1] = r3;
            }
            #pragma unroll
            for (int mt = 0; mt < 4; mt++)
                #pragma unroll
                for (int nt = 0; nt < 4; nt++)
                    mma16816(acc[mt][nt], afr[mt], bfr[nt]);
        }
    }
}

// ---------------------------------------------------------------------------
// prep: convert weights to bf16 (stacked fg + h) + zero colsum (every call)
// ---------------------------------------------------------------------------
__global__ __launch_bounds__(256)
void conv_w_kernel(const float* __restrict__ fw, const float* __restrict__ gw,
                   const float* __restrict__ hw,
                   __nv_bfloat16* __restrict__ fgw, __nv_bfloat16* __restrict__ hwb,
                   float* __restrict__ colsum)
{
    int i = blockIdx.x * 256 + threadIdx.x;
    if (i < BATCH * NN) colsum[i] = 0.0f;
    if (i < 128 * CC) {
        float v = (i < 64 * CC) ? fw[i] : gw[i - 64 * CC];
        fgw[i] = __float2bfloat16(v);
    }
    int j = i - 128 * CC;
    if (j >= 0 && j < CC * CC) hwb[j] = __float2bfloat16(hw[j]);
}

// ---------------------------------------------------------------------------
// prep: transpose x [b][k][n] fp32 -> xT [b][n][k] bf16
// ---------------------------------------------------------------------------
__global__ __launch_bounds__(256)
void transpose_x_kernel(const float* __restrict__ x, __nv_bfloat16* __restrict__ xT)
{
    __shared__ float t[32][33];
    const int b = blockIdx.z;
    const int n0 = blockIdx.x * 32, k0 = blockIdx.y * 32;
    const float* xb = x + (size_t)b * CC * NN;
    for (int r = threadIdx.y; r < 32; r += 8)
        t[r][threadIdx.x] = xb[(size_t)(k0 + r) * NN + n0 + threadIdx.x];
    __syncthreads();
    __nv_bfloat16* xo = xT + (size_t)b * NN * CC;
    for (int r = threadIdx.y; r < 32; r += 8)
        xo[(size_t)(n0 + r) * CC + k0 + threadIdx.x] = __float2bfloat16(t[threadIdx.x][r]);
}

// ---------------------------------------------------------------------------
// fg projection: D[o(128 stacked)][n(128)] over K=512; write fT/gT [n][o] bf16
// ---------------------------------------------------------------------------
__global__ __launch_bounds__(256)
void fg_proj_mma(const __nv_bfloat16* __restrict__ fgw, const __nv_bfloat16* __restrict__ xT,
                 const float* __restrict__ f_b, const float* __restrict__ g_b,
                 __nv_bfloat16* __restrict__ fT, __nv_bfloat16* __restrict__ gT)
{
    extern __shared__ char dsm[];
    const int b = blockIdx.z, n0 = blockIdx.x * 128;
    const int lane = threadIdx.x & 31, wid = threadIdx.x >> 5;
    const int wm = (wid >> 2) * 64, wn = (wid & 3) * 32;

    float acc[4][4][4] = {};
    gemm_core(fgw, CC, xT + (size_t)(b * NN + n0) * CC, CC, CC / 32, acc, dsm);

    __nv_bfloat16* fTb = fT + (size_t)b * NN * OO;
    __nv_bfloat16* gTb = gT + (size_t)b * NN * OO;
    #pragma unroll
    for (int mt = 0; mt < 4; mt++) {
        #pragma unroll
        for (int half = 0; half < 2; half++) {
            int o = wm + mt * 16 + (lane >> 2) + half * 8;
            float bias = (o < 64) ? f_b[o] : g_b[o - 64];
            __nv_bfloat16* dst = (o < 64) ? (fTb + o) : (gTb + (o - 64));
            #pragma unroll
            for (int nt = 0; nt < 4; nt++) {
                int n = n0 + wn + nt * 8 + (lane & 3) * 2;
                dst[(size_t)n * OO]       = __float2bfloat16(acc[mt][nt][half * 2]     + bias);
                dst[(size_t)(n + 1) * OO] = __float2bfloat16(acc[mt][nt][half * 2 + 1] + bias);
            }
        }
    }
}

// ---------------------------------------------------------------------------
// h projection: D[c(128)][n(128)] over K=512; write hB [c][n] bf16
// ---------------------------------------------------------------------------
__global__ __launch_bounds__(256)
void h_proj_mma(const __nv_bfloat16* __restrict__ hwb, const __nv_bfloat16* __restrict__ xT,
                const float* __restrict__ h_b, __nv_bfloat16* __restrict__ hB)
{
    extern __shared__ char dsm[];
    const int b = blockIdx.z, c0 = blockIdx.y * 128, n0 = blockIdx.x * 128;
    const int lane = threadIdx.x & 31, wid = threadIdx.x >> 5;
    const int wm = (wid >> 2) * 64, wn = (wid & 3) * 32;

    float acc[4][4][4] = {};
    gemm_core(hwb + (size_t)c0 * CC, CC,
              xT + (size_t)(b * NN + n0) * CC, CC, CC / 32, acc, dsm);

    __nv_bfloat16* hb = hB + (size_t)b * CC * NN;
    #pragma unroll
    for (int mt = 0; mt < 4; mt++) {
        #pragma unroll
        for (int half = 0; half < 2; half++) {
            int c = c0 + wm + mt * 16 + (lane >> 2) + half * 8;
            float bias = h_b[c];
            #pragma unroll
            for (int nt = 0; nt < 4; nt++) {
                int n = n0 + wn + nt * 8 + (lane & 3) * 2;
                __nv_bfloat162 v;
                v.x = __float2bfloat16(acc[mt][nt][half * 2]     + bias);
                v.y = __float2bfloat16(acc[mt][nt][half * 2 + 1] + bias);
                *(__nv_bfloat162*)(hb + (size_t)c * NN + n) = v;
            }
        }
    }
}

// ---------------------------------------------------------------------------
// scores+exp+transpose: e[i][j] = exp(fT[i,:].gT[j,:]); write eT[j][i] bf16;
// atomically accumulate colsum[j] = sum_i e[i][j].
// grid: (NN/128 [j], NN/128 [i], BATCH)
// ---------------------------------------------------------------------------
#define SPITCH 136   // bf16 elems per smem row (272B, 16B aligned)

__global__ __launch_bounds__(256)
void scores_mma(const __nv_bfloat16* __restrict__ fT, const __nv_bfloat16* __restrict__ gT,
                __nv_bfloat16* __restrict__ eT, float* __restrict__ colsum)
{
    extern __shared__ char dsm[];
    const int b = blockIdx.z, i0 = blockIdx.y * 128, j0 = blockIdx.x * 128;
    const int tid = threadIdx.x;
    const int lane = tid & 31, wid = tid >> 5;
    const int wm = (wid >> 2) * 64, wn = (wid & 3) * 32;

    float acc[4][4][4] = {};
    gemm_core(fT + (size_t)(b * NN + i0) * OO, OO,
              gT + (size_t)(b * NN + j0) * OO, OO, OO / 32, acc, dsm);

    __syncthreads();   // done with pipeline smem; reuse as transpose buffer
    __nv_bfloat16* ts = (__nv_bfloat16*)dsm;   // [128][SPITCH]

    // exp + transposed store into smem: ts[j][i] = bf16(exp(score[i][j]))
    #pragma unroll
    for (int mt = 0; mt < 4; mt++) {
        #pragma unroll
        for (int half = 0; half < 2; half++) {
            int i = wm + mt * 16 + (lane >> 2) + half * 8;
            #pragma unroll
            for (int nt = 0; nt < 4; nt++) {
                int j = wn + nt * 8 + (lane & 3) * 2;
                ts[(size_t)j * SPITCH + i]       =
                    __float2bfloat16(__expf(acc[mt][nt][half * 2]));
                ts[(size_t)(j + 1) * SPITCH + i] =
                    __float2bfloat16(__expf(acc[mt][nt][half * 2 + 1]));
            }
        }
    }
    __syncthreads();

    // coalesced write: eT[b][j0+j][i0+i], row j = 128 bf16 = 16 x uint4
    __nv_bfloat16* eb = eT + (size_t)b * NN * NN + (size_t)j0 * NN + i0;
    #pragma unroll
    for (int p = 0; p < 8; p++) {
        int lin = tid + p * 256;
        int row = lin >> 4, u = lin & 15;
        uint4 v = *(const uint4*)(ts + (size_t)row * SPITCH + u * 8);
        *(uint4*)(eb + (size_t)row * NN + u * 8) = v;
    }

    // partial column sums: thread pair (j, half) sums 64 values
    {
        int j = tid >> 1, hf = tid & 1;
        const __nv_bfloat16* rowp = ts + (size_t)j * SPITCH + hf * 64;
        float s = 0.0f;
        #pragma unroll
        for (int u = 0; u < 8; u++) {
            uint4 v = *(const uint4*)(rowp + u * 8);
            const __nv_bfloat162* h2 = (const __nv_bfloat162*)&v;
            #pragma unroll
            for (int q = 0; q < 4; q++) {
                float2 f2 = __bfloat1622float2(h2[q]);
                s += f2.x + f2.y;
            }
        }
        s += __shfl_xor_sync(0xffffffff, s, 1);
        if (hf == 0) atomicAdd(&colsum[b * NN + j0 + j], s);
    }
}

// ---------------------------------------------------------------------------
// attn: D[c(128)][m(128)] = sum_n hB[c][n]*eT[m][n] over K=4096
// epilogue: out = gamma * D / colsum[m] + x
// ---------------------------------------------------------------------------
__global__ __launch_bounds__(256)
void attn_mma(const __nv_bfloat16* __restrict__ hB, const __nv_bfloat16* __restrict__ eT,
              const float* __restrict__ colsum,
              const float* __restrict__ x, const float* __restrict__ gamma_p,
              float* __restrict__ out)
{
    extern __shared__ char dsm[];
    const int b = blockIdx.z, c0 = blockIdx.y * 128, m0 = blockIdx.x * 128;
    const int lane = threadIdx.x & 31, wid = threadIdx.x >> 5;
    const int wm = (wid >> 2) * 64, wn = (wid & 3) * 32;

    float acc[4][4][4] = {};
    gemm_core(hB + ((size_t)b * CC + c0) * NN, NN,
              eT + ((size_t)b * NN + m0) * NN, NN, NN / 32, acc, dsm);

    const float gamma = *gamma_p;

    // per-thread inverse sums for the 8 m-columns this thread owns
    float inv[4][2];
    #pragma unroll
    for (int nt = 0; nt < 4; nt++) {
        int m = m0 + wn + nt * 8 + (lane & 3) * 2;
        inv[nt][0] = gamma / colsum[b * NN + m];
        inv[nt][1] = gamma / colsum[b * NN + m + 1];
    }

    #pragma unroll
    for (int mt = 0; mt < 4; mt++) {
        #pragma unroll
        for (int half = 0; half < 2; half++) {
            int c = c0 + wm + mt * 16 + (lane >> 2) + half * 8;
            size_t rowb = ((size_t)b * CC + c) * NN;
            #pragma unroll
            for (int nt = 0; nt < 4; nt++) {
                int m = m0 + wn + nt * 8 + (lane & 3) * 2;
                float2 xv = *(const float2*)(x + rowb + m);
                float2 ov;
                ov.x = acc[mt][nt][half * 2]     * inv[nt][0] + xv.x;
                ov.y = acc[mt][nt][half * 2 + 1] * inv[nt][1] + xv.y;
                *(float2*)(out + rowb + m) = ov;
            }
        }
    }
}

// ---------------------------------------------------------------------------
extern "C" void kernel_launch(void* const* d_in, const int* in_sizes, int n_in,
                              void* d_out, int out_size)
{
    const float* x     = (const float*)d_in[0];
    const float* f_w   = (const float*)d_in[1];
    const float* f_b   = (const float*)d_in[2];
    const float* g_w   = (const float*)d_in[3];
    const float* g_b   = (const float*)d_in[4];
    const float* h_w   = (const float*)d_in[5];
    const float* h_b   = (const float*)d_in[6];
    const float* gamma = (const float*)d_in[7];
    float* out = (float*)d_out;

    __nv_bfloat16 *pxT, *pfgw, *phw, *pfT, *pgT, *phB, *peT;
    float *psum;
    cudaGetSymbolAddress((void**)&pxT,  d_xT);
    cudaGetSymbolAddress((void**)&pfgw, d_fgw);
    cudaGetSymbolAddress((void**)&phw,  d_hw);
    cudaGetSymbolAddress((void**)&pfT,  d_fT);
    cudaGetSymbolAddress((void**)&pgT,  d_gT);
    cudaGetSymbolAddress((void**)&phB,  d_hB);
    cudaGetSymbolAddress((void**)&peT,  d_eT);
    cudaGetSymbolAddress((void**)&psum, d_colsum);

    // unconditional every call — deterministic, no static guards
    cudaFuncSetAttribute(fg_proj_mma, cudaFuncAttributeMaxDynamicSharedMemorySize, SMEM_DYN);
    cudaFuncSetAttribute(h_proj_mma,  cudaFuncAttributeMaxDynamicSharedMemorySize, SMEM_DYN);
    cudaFuncSetAttribute(scores_mma,  cudaFuncAttributeMaxDynamicSharedMemorySize, SMEM_DYN);
    cudaFuncSetAttribute(attn_mma,    cudaFuncAttributeMaxDynamicSharedMemorySize, SMEM_DYN);

    // prep (also zeroes colsum each call)
    conv_w_kernel<<<1280, 256>>>(f_w, g_w, h_w, pfgw, phw, psum);
    transpose_x_kernel<<<dim3(NN / 32, CC / 32, BATCH), dim3(32, 8)>>>(x, pxT);

    // projections (mma.sync)
    fg_proj_mma<<<dim3(NN / 128, 1, BATCH), 256, SMEM_DYN>>>(pfgw, pxT, f_b, g_b, pfT, pgT);
    h_proj_mma <<<dim3(NN / 128, CC / 128, BATCH), 256, SMEM_DYN>>>(phw, pxT, h_b, phB);

    // scores -> exp -> transposed bf16 + column sums (fused)
    scores_mma<<<dim3(NN / 128, NN / 128, BATCH), 256, SMEM_DYN>>>(pfT, pgT, peT, psum);

    // attention GEMM + normalize-in-epilogue
    attn_mma<<<dim3(NN / 128, CC / 128, BATCH), 256, SMEM_DYN>>>(
        phB, peT, psum, x, gamma, out);
}